// round 1
// baseline (speedup 1.0000x reference)
#include <cuda_runtime.h>
#include <math.h>

#define S_SEQ 256
#define R_RES 256
#define CM 256
#define CZ 128
#define NH 8
#define CH 32
#define HC 256
#define LNEPS 1e-5f

// ---------------- scratch (device globals; no allocation allowed) ----------------
__device__ float g_mn[(size_t)S_SEQ * R_RES * CM];       // 64 MB  LN(m)
__device__ float g_q[(size_t)S_SEQ * NH * R_RES * CH];   // 64 MB  (s,h,r,c)
__device__ float g_k[(size_t)S_SEQ * NH * R_RES * CH];   // 64 MB
__device__ float g_v[(size_t)S_SEQ * NH * R_RES * CH];   // 64 MB
__device__ float g_gate[(size_t)S_SEQ * R_RES * HC];     // 64 MB  sigmoid(mn@Wg+bg)
__device__ float g_o[(size_t)S_SEQ * R_RES * HC];        // 64 MB  attention out (s,r,h*c)
__device__ float g_bias[(size_t)NH * R_RES * R_RES];     //  2 MB  layout [h][k][q]

// ---------------- LayerNorm over m rows (C_M = 256) ----------------
__global__ void ln_m_kernel(const float* __restrict__ x, const float* __restrict__ w,
                            const float* __restrict__ b) {
    int row = blockIdx.x;          // s*R + r
    int t = threadIdx.x;           // 0..255
    float v = x[(size_t)row * CM + t];
    __shared__ float rs[256], rq[256];
    rs[t] = v; rq[t] = v * v;
    __syncthreads();
    for (int st = 128; st > 0; st >>= 1) {
        if (t < st) { rs[t] += rs[t + st]; rq[t] += rq[t + st]; }
        __syncthreads();
    }
    float mean = rs[0] * (1.0f / CM);
    float var  = rq[0] * (1.0f / CM) - mean * mean;
    float inv  = rsqrtf(var + LNEPS);
    g_mn[(size_t)row * CM + t] = (v - mean) * inv * w[t] + b[t];
}

// ---------------- LayerNorm over z rows (C_Z = 128) fused with pair-bias projection ----------------
// bias[h][q][k] = sum_z zn[q][k][z] * Wz[z][h]; stored as g_bias[(h*R + k)*R + q]
__global__ void ln_z_bias_kernel(const float* __restrict__ z, const float* __restrict__ w,
                                 const float* __restrict__ b, const float* __restrict__ Wz) {
    int qk = blockIdx.x;           // q*R + k
    int q = qk >> 8, k = qk & 255;
    int t = threadIdx.x;           // 0..127
    float v = z[(size_t)qk * CZ + t];
    __shared__ float rs[128], rq[128];
    rs[t] = v; rq[t] = v * v;
    __syncthreads();
    for (int st = 64; st > 0; st >>= 1) {
        if (t < st) { rs[t] += rs[t + st]; rq[t] += rq[t + st]; }
        __syncthreads();
    }
    float mean = rs[0] * (1.0f / CZ);
    float var  = rq[0] * (1.0f / CZ) - mean * mean;
    float zn   = (v - mean) * rsqrtf(var + LNEPS) * w[t] + b[t];

    __shared__ float red[128 * 8];
#pragma unroll
    for (int h = 0; h < 8; h++) red[t * 8 + h] = zn * Wz[t * 8 + h];
    __syncthreads();
    for (int st = 64; st > 0; st >>= 1) {
        if (t < st) {
#pragma unroll
            for (int h = 0; h < 8; h++) red[t * 8 + h] += red[(t + st) * 8 + h];
        }
        __syncthreads();
    }
    if (t < 8) g_bias[((size_t)t * R_RES + k) * R_RES + q] = red[t];
}

// ---------------- SGEMM: C(65536x256) = A(65536x256) @ B(256x256), 128x128x8 tiles ----------------
// mode 1: A = g_mn, out = q/k/v (outsel), permuted store (s,h,r,c)
// mode 2: A = g_mn, out = g_gate, epilogue sigmoid(x + bias[n])
// mode 3: A = g_gate .* g_o,   out = out_ext, epilogue + bias[n]
__global__ void __launch_bounds__(256, 2) sgemm_kernel(
    const float* __restrict__ B, const float* __restrict__ bias,
    float* __restrict__ out_ext, int mode, int outsel) {

    const float* A  = (mode == 3) ? g_gate : g_mn;
    const float* A2 = (mode == 3) ? g_o : nullptr;
    float* out;
    if (mode == 3)      out = out_ext;
    else if (mode == 2) out = g_gate;
    else                out = (outsel == 0) ? g_q : (outsel == 1) ? g_k : g_v;

    __shared__ float As[8][128];
    __shared__ float Bs[8][128];

    int tid = threadIdx.x;
    int bx = blockIdx.x, by = blockIdx.y;
    int arow = tid >> 1, acol = (tid & 1) * 4;
    int brow = tid >> 5, bcol = (tid & 31) * 4;
    int ty = tid >> 4, tx = tid & 15;

    const float* Ap  = A + ((size_t)by * 128 + arow) * 256 + acol;
    const float* A2p = A2 ? A2 + ((size_t)by * 128 + arow) * 256 + acol : nullptr;
    const float* Bp  = B + (size_t)brow * 256 + bx * 128 + bcol;

    float4 av = *(const float4*)Ap;
    if (A2) {
        float4 g2 = *(const float4*)A2p;
        av.x *= g2.x; av.y *= g2.y; av.z *= g2.z; av.w *= g2.w;
    }
    float4 bv = *(const float4*)Bp;

    float acc[8][8];
#pragma unroll
    for (int i = 0; i < 8; i++)
#pragma unroll
        for (int j = 0; j < 8; j++) acc[i][j] = 0.f;

    for (int k0 = 0; k0 < 256; k0 += 8) {
        As[acol + 0][arow] = av.x;
        As[acol + 1][arow] = av.y;
        As[acol + 2][arow] = av.z;
        As[acol + 3][arow] = av.w;
        *(float4*)&Bs[brow][bcol] = bv;
        __syncthreads();

        if (k0 < 248) {   // register-prefetch next tile
            av = *(const float4*)(Ap + k0 + 8);
            if (A2) {
                float4 g2 = *(const float4*)(A2p + k0 + 8);
                av.x *= g2.x; av.y *= g2.y; av.z *= g2.z; av.w *= g2.w;
            }
            bv = *(const float4*)(Bp + (size_t)(k0 + 8) * 256);
        }

#pragma unroll
        for (int kk = 0; kk < 8; kk++) {
            float a[8], bb[8];
            *(float4*)&a[0]  = *(const float4*)&As[kk][ty * 4];
            *(float4*)&a[4]  = *(const float4*)&As[kk][ty * 4 + 64];
            *(float4*)&bb[0] = *(const float4*)&Bs[kk][tx * 4];
            *(float4*)&bb[4] = *(const float4*)&Bs[kk][tx * 4 + 64];
#pragma unroll
            for (int i = 0; i < 8; i++)
#pragma unroll
                for (int j = 0; j < 8; j++)
                    acc[i][j] = fmaf(a[i], bb[j], acc[i][j]);
        }
        __syncthreads();
    }

    // epilogue
#pragma unroll
    for (int i = 0; i < 8; i++) {
        int m = by * 128 + ty * 4 + ((i < 4) ? i : 60 + i);   // rows ty*4+{0..3}, ty*4+64+{0..3}
#pragma unroll
        for (int jg = 0; jg < 2; jg++) {
            int n = bx * 128 + tx * 4 + jg * 64;
            float4 val;
            val.x = acc[i][jg * 4 + 0];
            val.y = acc[i][jg * 4 + 1];
            val.z = acc[i][jg * 4 + 2];
            val.w = acc[i][jg * 4 + 3];
            if (mode == 2) {
                val.x = 1.f / (1.f + __expf(-(val.x + bias[n + 0])));
                val.y = 1.f / (1.f + __expf(-(val.y + bias[n + 1])));
                val.z = 1.f / (1.f + __expf(-(val.z + bias[n + 2])));
                val.w = 1.f / (1.f + __expf(-(val.w + bias[n + 3])));
            } else if (mode == 3) {
                val.x += bias[n + 0];
                val.y += bias[n + 1];
                val.z += bias[n + 2];
                val.w += bias[n + 3];
            }
            if (mode == 1) {
                int s = m >> 8, r = m & 255, h = n >> 5, c = n & 31;
                *(float4*)(out + (((size_t)(s * NH + h) * R_RES + r) * CH + c)) = val;
            } else {
                *(float4*)(out + (size_t)m * 256 + n) = val;
            }
        }
    }
}

// ---------------- flash-style attention: one block per (s,h), one thread per query row ----------------
__global__ void __launch_bounds__(256) attn_kernel() {
    int sh = blockIdx.x;              // s*NH + h
    int s = sh >> 3, h = sh & 7;
    int qr = threadIdx.x;             // query row 0..255

    __shared__ float ksh[64 * 32];
    __shared__ float vsh[64 * 32];

    const float* qp = g_q + ((size_t)sh * R_RES + qr) * CH;
    float qv[32];
#pragma unroll
    for (int c = 0; c < 32; c += 4) {
        float4 t4 = *(const float4*)(qp + c);
        qv[c] = t4.x; qv[c + 1] = t4.y; qv[c + 2] = t4.z; qv[c + 3] = t4.w;
    }

    float mmax = -3.0e38f, l = 0.f;
    float o[32];
#pragma unroll
    for (int c = 0; c < 32; c++) o[c] = 0.f;

    const float scale = 0.17677669529663687f;   // 1/sqrt(32)
    const float* bp = g_bias + (size_t)h * R_RES * R_RES + qr;   // [h][k][qr]

    for (int k0 = 0; k0 < R_RES; k0 += 64) {
        __syncthreads();
        const float* kb = g_k + ((size_t)sh * R_RES + k0) * CH;
        const float* vb = g_v + ((size_t)sh * R_RES + k0) * CH;
        for (int i = threadIdx.x; i < 64 * 32 / 4; i += 256) {
            ((float4*)ksh)[i] = ((const float4*)kb)[i];
            ((float4*)vsh)[i] = ((const float4*)vb)[i];
        }
        __syncthreads();

        for (int kk = 0; kk < 64; kk++) {
            float sc = bp[(size_t)(k0 + kk) * R_RES];   // coalesced over qr, L2-resident
            float dot = 0.f;
#pragma unroll
            for (int c = 0; c < 32; c++) dot = fmaf(qv[c], ksh[kk * 32 + c], dot);
            sc = fmaf(dot, scale, sc);
            if (sc > mmax) {                  // rare after warm-up (scores are small)
                float corr = __expf(mmax - sc);
                mmax = sc;
                l *= corr;
#pragma unroll
                for (int c = 0; c < 32; c++) o[c] *= corr;
            }
            float p = __expf(sc - mmax);
            l += p;
#pragma unroll
            for (int c = 0; c < 32; c++) o[c] = fmaf(p, vsh[kk * 32 + c], o[c]);
        }
    }

    float inv = 1.0f / l;
    float* op = g_o + ((size_t)(s * R_RES + qr)) * HC + h * CH;
#pragma unroll
    for (int c = 0; c < 32; c += 4) {
        float4 v4;
        v4.x = o[c] * inv; v4.y = o[c + 1] * inv;
        v4.z = o[c + 2] * inv; v4.w = o[c + 3] * inv;
        *(float4*)(op + c) = v4;
    }
}

// ---------------- launch ----------------
extern "C" void kernel_launch(void* const* d_in, const int* in_sizes, int n_in,
                              void* d_out, int out_size) {
    (void)in_sizes; (void)n_in; (void)out_size;
    const float* m   = (const float*)d_in[0];
    const float* z   = (const float*)d_in[1];
    const float* lmw = (const float*)d_in[2];
    const float* lmb = (const float*)d_in[3];
    const float* lzw = (const float*)d_in[4];
    const float* lzb = (const float*)d_in[5];
    const float* Wz  = (const float*)d_in[6];
    const float* Wq  = (const float*)d_in[7];
    const float* Wk  = (const float*)d_in[8];
    const float* Wv  = (const float*)d_in[9];
    const float* Wg  = (const float*)d_in[10];
    const float* bg  = (const float*)d_in[11];
    const float* Wo  = (const float*)d_in[12];
    const float* bo  = (const float*)d_in[13];

    ln_m_kernel<<<S_SEQ * R_RES, 256>>>(m, lmw, lmb);
    ln_z_bias_kernel<<<R_RES * R_RES, 128>>>(z, lzw, lzb, Wz);

    dim3 gg(2, 512);   // N/128, M/128
    sgemm_kernel<<<gg, 256>>>(Wq, nullptr, nullptr, 1, 0);
    sgemm_kernel<<<gg, 256>>>(Wk, nullptr, nullptr, 1, 1);
    sgemm_kernel<<<gg, 256>>>(Wv, nullptr, nullptr, 1, 2);
    sgemm_kernel<<<gg, 256>>>(Wg, bg, nullptr, 2, 0);

    attn_kernel<<<S_SEQ * NH, 256>>>();

    sgemm_kernel<<<gg, 256>>>(Wo, bo, (float*)d_out, 3, 0);
}

// round 2
// speedup vs baseline: 1.1960x; 1.1960x over previous
#include <cuda_runtime.h>
#include <math.h>
#include <stdint.h>

#define S_SEQ 256
#define R_RES 256
#define CM 256
#define CZ 128
#define NH 8
#define CH 32
#define HC 256
#define LNEPS 1e-5f

// ---------------- scratch (device globals; no allocation allowed) ----------------
__device__ float g_mn[(size_t)S_SEQ * R_RES * CM];       // 64 MB  LN(m)
__device__ float g_q[(size_t)S_SEQ * NH * R_RES * CH];   // 64 MB  (s,h,r,c)
__device__ float g_k[(size_t)S_SEQ * NH * R_RES * CH];   // 64 MB
__device__ float g_v[(size_t)S_SEQ * NH * R_RES * CH];   // 64 MB
__device__ float g_gate[(size_t)S_SEQ * R_RES * HC];     // 64 MB  sigmoid(mn@Wg+bg)
__device__ float g_o[(size_t)S_SEQ * R_RES * HC];        // 64 MB  attention out (s,r,h*c)
__device__ float g_bias[(size_t)NH * R_RES * R_RES];     //  2 MB  layout [h][k][q]

__device__ __forceinline__ float ftf32(float x) {
    uint32_t u;
    asm("cvt.rna.tf32.f32 %0, %1;" : "=r"(u) : "f"(x));
    return __uint_as_float(u);
}

// ---------------- LayerNorm over m rows (C_M = 256) ----------------
__global__ void ln_m_kernel(const float* __restrict__ x, const float* __restrict__ w,
                            const float* __restrict__ b) {
    int row = blockIdx.x;          // s*R + r
    int t = threadIdx.x;           // 0..255
    float v = x[(size_t)row * CM + t];
    __shared__ float rs[256], rq[256];
    rs[t] = v; rq[t] = v * v;
    __syncthreads();
    for (int st = 128; st > 0; st >>= 1) {
        if (t < st) { rs[t] += rs[t + st]; rq[t] += rq[t + st]; }
        __syncthreads();
    }
    float mean = rs[0] * (1.0f / CM);
    float var  = rq[0] * (1.0f / CM) - mean * mean;
    float inv  = rsqrtf(var + LNEPS);
    g_mn[(size_t)row * CM + t] = (v - mean) * inv * w[t] + b[t];
}

// ---------------- LayerNorm over z rows (C_Z = 128) fused with pair-bias projection ----------------
// bias[h][q][k] = sum_z zn[q][k][z] * Wz[z][h]; stored as g_bias[(h*R + k)*R + q]
__global__ void ln_z_bias_kernel(const float* __restrict__ z, const float* __restrict__ w,
                                 const float* __restrict__ b, const float* __restrict__ Wz) {
    int qk = blockIdx.x;           // q*R + k
    int q = qk >> 8, k = qk & 255;
    int t = threadIdx.x;           // 0..127
    float v = z[(size_t)qk * CZ + t];
    __shared__ float rs[128], rq[128];
    rs[t] = v; rq[t] = v * v;
    __syncthreads();
    for (int st = 64; st > 0; st >>= 1) {
        if (t < st) { rs[t] += rs[t + st]; rq[t] += rq[t + st]; }
        __syncthreads();
    }
    float mean = rs[0] * (1.0f / CZ);
    float var  = rq[0] * (1.0f / CZ) - mean * mean;
    float zn   = (v - mean) * rsqrtf(var + LNEPS) * w[t] + b[t];

    __shared__ float red[128 * 8];
#pragma unroll
    for (int h = 0; h < 8; h++) red[t * 8 + h] = zn * Wz[t * 8 + h];
    __syncthreads();
    for (int st = 64; st > 0; st >>= 1) {
        if (t < st) {
#pragma unroll
            for (int h = 0; h < 8; h++) red[t * 8 + h] += red[(t + st) * 8 + h];
        }
        __syncthreads();
    }
    if (t < 8) g_bias[((size_t)t * R_RES + k) * R_RES + q] = red[t];
}

// ---------------- tf32 tensor-core GEMM: C(65536x256) = A(65536x256) @ B(256x256) ----------------
// CTA tile 128x64, BK=32, 8 warps (4m x 2n), warp tile 32x32, mma.m16n8k8.tf32.
// mode 1: A = g_mn, out = q/k/v (outsel), permuted store (s,h,r,c)
// mode 2: A = g_mn, out = g_gate, epilogue sigmoid(x + bias[n])
// mode 3: A = g_gate .* g_o, out = out_ext, epilogue + bias[n]
#define MMA4(d, a, b)                                                              \
    asm volatile("mma.sync.aligned.m16n8k8.row.col.f32.tf32.tf32.f32 "             \
                 "{%0,%1,%2,%3},{%4,%5,%6,%7},{%8,%9},{%0,%1,%2,%3};"              \
                 : "+f"(d[0]), "+f"(d[1]), "+f"(d[2]), "+f"(d[3])                  \
                 : "r"(a[0]), "r"(a[1]), "r"(a[2]), "r"(a[3]), "r"(b[0]), "r"(b[1]))

__global__ void __launch_bounds__(256, 2) tf32gemm_kernel(
    const float* __restrict__ Bw, const float* __restrict__ bias,
    float* __restrict__ out_ext, int mode, int outsel) {

    const float* A  = (mode == 3) ? g_gate : g_mn;
    const float* A2 = (mode == 3) ? g_o : nullptr;
    float* out;
    if (mode == 3)      out = out_ext;
    else if (mode == 2) out = g_gate;
    else                out = (outsel == 0) ? g_q : (outsel == 1) ? g_k : g_v;

    __shared__ __align__(16) float As[128 * 36];  // [m][k] stride 36 -> conflict-free frags
    __shared__ __align__(16) float Bs[32 * 72];   // [k][n] stride 72 -> conflict-free frags

    const int tid  = threadIdx.x;
    const int lane = tid & 31, wid = tid >> 5;
    const int gid  = lane >> 2, tg = lane & 3;
    const int wm   = (wid & 3) * 32;      // warp m-offset in CTA tile
    const int wn   = (wid >> 2) * 32;     // warp n-offset
    const int bx   = blockIdx.x, by = blockIdx.y;

    // global->smem load assignments
    const int a_row = tid >> 1;            // 0..127
    const int a_col = (tid & 1) * 16;      // 16 consecutive floats
    const int b_row = tid >> 3;            // 0..31
    const int b_col = (tid & 7) * 8;       // 8 consecutive floats

    const float* Ap  = A + ((size_t)(by * 128 + a_row)) * 256 + a_col;
    const float* A2p = A2 ? A2 + ((size_t)(by * 128 + a_row)) * 256 + a_col : nullptr;
    const float* Bp  = Bw + (size_t)b_row * 256 + bx * 64 + b_col;

    float4 ar[4], br[2];
#pragma unroll
    for (int i = 0; i < 4; i++) ar[i] = ((const float4*)Ap)[i];
    if (A2) {
#pragma unroll
        for (int i = 0; i < 4; i++) {
            float4 g2 = ((const float4*)A2p)[i];
            ar[i].x *= g2.x; ar[i].y *= g2.y; ar[i].z *= g2.z; ar[i].w *= g2.w;
        }
    }
#pragma unroll
    for (int i = 0; i < 2; i++) br[i] = ((const float4*)Bp)[i];

    float acc[2][4][4];
#pragma unroll
    for (int mt = 0; mt < 2; mt++)
#pragma unroll
        for (int nt = 0; nt < 4; nt++)
#pragma unroll
            for (int j = 0; j < 4; j++) acc[mt][nt][j] = 0.f;

    for (int k0 = 0; k0 < 256; k0 += 32) {
        // store tile (converted to tf32)
#pragma unroll
        for (int i = 0; i < 4; i++) {
            float4 v = ar[i];
            v.x = ftf32(v.x); v.y = ftf32(v.y); v.z = ftf32(v.z); v.w = ftf32(v.w);
            *(float4*)&As[a_row * 36 + a_col + 4 * i] = v;
        }
#pragma unroll
        for (int i = 0; i < 2; i++) {
            float4 v = br[i];
            v.x = ftf32(v.x); v.y = ftf32(v.y); v.z = ftf32(v.z); v.w = ftf32(v.w);
            *(float4*)&Bs[b_row * 72 + b_col + 4 * i] = v;
        }
        __syncthreads();

        if (k0 < 224) {  // register prefetch next k-tile
#pragma unroll
            for (int i = 0; i < 4; i++) ar[i] = ((const float4*)(Ap + k0 + 32))[i];
            if (A2) {
#pragma unroll
                for (int i = 0; i < 4; i++) {
                    float4 g2 = ((const float4*)(A2p + k0 + 32))[i];
                    ar[i].x *= g2.x; ar[i].y *= g2.y; ar[i].z *= g2.z; ar[i].w *= g2.w;
                }
            }
#pragma unroll
            for (int i = 0; i < 2; i++) br[i] = ((const float4*)(Bp + (size_t)(k0 + 32) * 256))[i];
        }

#pragma unroll
        for (int ks = 0; ks < 4; ks++) {
            const int kb = ks * 8;
            uint32_t a[2][4], b[4][2];
#pragma unroll
            for (int mt = 0; mt < 2; mt++) {
                int r0 = wm + mt * 16 + gid;
                a[mt][0] = __float_as_uint(As[r0 * 36 + kb + tg]);
                a[mt][1] = __float_as_uint(As[(r0 + 8) * 36 + kb + tg]);
                a[mt][2] = __float_as_uint(As[r0 * 36 + kb + tg + 4]);
                a[mt][3] = __float_as_uint(As[(r0 + 8) * 36 + kb + tg + 4]);
            }
#pragma unroll
            for (int nt = 0; nt < 4; nt++) {
                int c0 = wn + nt * 8 + gid;
                b[nt][0] = __float_as_uint(Bs[(kb + tg) * 72 + c0]);
                b[nt][1] = __float_as_uint(Bs[(kb + tg + 4) * 72 + c0]);
            }
#pragma unroll
            for (int mt = 0; mt < 2; mt++)
#pragma unroll
                for (int nt = 0; nt < 4; nt++)
                    MMA4(acc[mt][nt], a[mt], b[nt]);
        }
        __syncthreads();
    }

    // ---- epilogue ----
#pragma unroll
    for (int mt = 0; mt < 2; mt++) {
#pragma unroll
        for (int nt = 0; nt < 4; nt++) {
#pragma unroll
            for (int half = 0; half < 2; half++) {
                int gr = by * 128 + wm + mt * 16 + gid + half * 8;
                int gc = bx * 64 + wn + nt * 8 + tg * 2;
                float2 val;
                val.x = acc[mt][nt][half * 2 + 0];
                val.y = acc[mt][nt][half * 2 + 1];
                if (mode == 2) {
                    val.x = 1.f / (1.f + __expf(-(val.x + bias[gc + 0])));
                    val.y = 1.f / (1.f + __expf(-(val.y + bias[gc + 1])));
                } else if (mode == 3) {
                    val.x += bias[gc + 0];
                    val.y += bias[gc + 1];
                }
                if (mode == 1) {
                    int s = gr >> 8, r = gr & 255, h = gc >> 5, c = gc & 31;
                    *(float2*)(out + (((size_t)(s * NH + h) * R_RES + r) * CH + c)) = val;
                } else {
                    *(float2*)(out + (size_t)gr * 256 + gc) = val;
                }
            }
        }
    }
}

// ---------------- flash-style attention: one block per (s,h), one thread per query row ----------------
__global__ void __launch_bounds__(256) attn_kernel() {
    int sh = blockIdx.x;              // s*NH + h
    int s = sh >> 3, h = sh & 7;
    int qr = threadIdx.x;             // query row 0..255

    __shared__ float ksh[128 * 32];
    __shared__ float vsh[128 * 32];

    const float* qp = g_q + ((size_t)sh * R_RES + qr) * CH;
    float qv[32];
#pragma unroll
    for (int c = 0; c < 32; c += 4) {
        float4 t4 = *(const float4*)(qp + c);
        qv[c] = t4.x; qv[c + 1] = t4.y; qv[c + 2] = t4.z; qv[c + 3] = t4.w;
    }

    float mmax = -3.0e38f, l = 0.f;
    float o[32];
#pragma unroll
    for (int c = 0; c < 32; c++) o[c] = 0.f;

    const float scale = 0.17677669529663687f;   // 1/sqrt(32)
    const float* bp = g_bias + (size_t)h * R_RES * R_RES + qr;   // [h][k][qr]

    for (int k0 = 0; k0 < R_RES; k0 += 128) {
        __syncthreads();
        const float* kb = g_k + ((size_t)sh * R_RES + k0) * CH;
        const float* vb = g_v + ((size_t)sh * R_RES + k0) * CH;
        for (int i = threadIdx.x; i < 128 * 32 / 4; i += 256) {
            ((float4*)ksh)[i] = ((const float4*)kb)[i];
            ((float4*)vsh)[i] = ((const float4*)vb)[i];
        }
        __syncthreads();

        float bnext = bp[(size_t)k0 * R_RES];
        for (int kk = 0; kk < 128; kk++) {
            float sc = bnext;
            if (kk < 127) bnext = bp[(size_t)(k0 + kk + 1) * R_RES];

            const float4* kp4 = (const float4*)(ksh + kk * 32);
            float d0 = 0.f, d1 = 0.f;
#pragma unroll
            for (int c = 0; c < 4; c++) {
                float4 ka = kp4[c];
                float4 kc = kp4[c + 4];
                d0 = fmaf(qv[4 * c + 0], ka.x, d0);
                d0 = fmaf(qv[4 * c + 1], ka.y, d0);
                d0 = fmaf(qv[4 * c + 2], ka.z, d0);
                d0 = fmaf(qv[4 * c + 3], ka.w, d0);
                d1 = fmaf(qv[16 + 4 * c + 0], kc.x, d1);
                d1 = fmaf(qv[16 + 4 * c + 1], kc.y, d1);
                d1 = fmaf(qv[16 + 4 * c + 2], kc.z, d1);
                d1 = fmaf(qv[16 + 4 * c + 3], kc.w, d1);
            }
            sc = fmaf(d0 + d1, scale, sc);
            if (sc > mmax) {
                float corr = __expf(mmax - sc);
                mmax = sc;
                l *= corr;
#pragma unroll
                for (int c = 0; c < 32; c++) o[c] *= corr;
            }
            float p = __expf(sc - mmax);
            l += p;
            const float4* vp4 = (const float4*)(vsh + kk * 32);
#pragma unroll
            for (int c = 0; c < 8; c++) {
                float4 vv = vp4[c];
                o[4 * c + 0] = fmaf(p, vv.x, o[4 * c + 0]);
                o[4 * c + 1] = fmaf(p, vv.y, o[4 * c + 1]);
                o[4 * c + 2] = fmaf(p, vv.z, o[4 * c + 2]);
                o[4 * c + 3] = fmaf(p, vv.w, o[4 * c + 3]);
            }
        }
    }

    float inv = 1.0f / l;
    float* op = g_o + ((size_t)(s * R_RES + qr)) * HC + h * CH;
#pragma unroll
    for (int c = 0; c < 32; c += 4) {
        float4 v4;
        v4.x = o[c] * inv; v4.y = o[c + 1] * inv;
        v4.z = o[c + 2] * inv; v4.w = o[c + 3] * inv;
        *(float4*)(op + c) = v4;
    }
}

// ---------------- launch ----------------
extern "C" void kernel_launch(void* const* d_in, const int* in_sizes, int n_in,
                              void* d_out, int out_size) {
    (void)in_sizes; (void)n_in; (void)out_size;
    const float* m   = (const float*)d_in[0];
    const float* z   = (const float*)d_in[1];
    const float* lmw = (const float*)d_in[2];
    const float* lmb = (const float*)d_in[3];
    const float* lzw = (const float*)d_in[4];
    const float* lzb = (const float*)d_in[5];
    const float* Wz  = (const float*)d_in[6];
    const float* Wq  = (const float*)d_in[7];
    const float* Wk  = (const float*)d_in[8];
    const float* Wv  = (const float*)d_in[9];
    const float* Wg  = (const float*)d_in[10];
    const float* bg  = (const float*)d_in[11];
    const float* Wo  = (const float*)d_in[12];
    const float* bo  = (const float*)d_in[13];

    ln_m_kernel<<<S_SEQ * R_RES, 256>>>(m, lmw, lmb);
    ln_z_bias_kernel<<<R_RES * R_RES, 128>>>(z, lzw, lzb, Wz);

    dim3 gg(4, 512);   // N/64, M/128
    tf32gemm_kernel<<<gg, 256>>>(Wq, nullptr, nullptr, 1, 0);
    tf32gemm_kernel<<<gg, 256>>>(Wk, nullptr, nullptr, 1, 1);
    tf32gemm_kernel<<<gg, 256>>>(Wv, nullptr, nullptr, 1, 2);
    tf32gemm_kernel<<<gg, 256>>>(Wg, bg, nullptr, 2, 0);

    attn_kernel<<<S_SEQ * NH, 256>>>();

    tf32gemm_kernel<<<gg, 256>>>(Wo, bo, (float*)d_out, 3, 0);
}

// round 3
// speedup vs baseline: 1.6625x; 1.3901x over previous
#include <cuda_runtime.h>
#include <math.h>
#include <stdint.h>

#define S_SEQ 256
#define R_RES 256
#define CM 256
#define CZ 128
#define NH 8
#define CH 32
#define HC 256
#define LNEPS 1e-5f

// ---------------- scratch (device globals; no allocation allowed) ----------------
__device__ float g_mn[(size_t)S_SEQ * R_RES * CM];       // 64 MB  LN(m)
__device__ float g_q[(size_t)S_SEQ * NH * R_RES * CH];   // 64 MB  (s,h,r,c)
__device__ float g_k[(size_t)S_SEQ * NH * R_RES * CH];   // 64 MB
__device__ float g_v[(size_t)S_SEQ * NH * R_RES * CH];   // 64 MB
__device__ float g_gate[(size_t)S_SEQ * R_RES * HC];     // 64 MB  sigmoid(mn@Wg+bg)
__device__ float g_o[(size_t)S_SEQ * R_RES * HC];        // 64 MB  attention out (s,r,h*c)
__device__ float g_bias[(size_t)NH * R_RES * R_RES];     //  2 MB  layout [h][q][k]

__device__ __forceinline__ float ftf32(float x) {
    uint32_t u;
    asm("cvt.rna.tf32.f32 %0, %1;" : "=r"(u) : "f"(x));
    return __uint_as_float(u);
}
__device__ __forceinline__ uint32_t ftf32u(float x) {
    uint32_t u;
    asm("cvt.rna.tf32.f32 %0, %1;" : "=r"(u) : "f"(x));
    return u;
}

#define MMA4(d, a, b)                                                              \
    asm volatile("mma.sync.aligned.m16n8k8.row.col.f32.tf32.tf32.f32 "             \
                 "{%0,%1,%2,%3},{%4,%5,%6,%7},{%8,%9},{%0,%1,%2,%3};"              \
                 : "+f"(d[0]), "+f"(d[1]), "+f"(d[2]), "+f"(d[3])                  \
                 : "r"(a[0]), "r"(a[1]), "r"(a[2]), "r"(a[3]), "r"(b[0]), "r"(b[1]))

// ---------------- LayerNorm over m rows (C_M = 256) ----------------
__global__ void ln_m_kernel(const float* __restrict__ x, const float* __restrict__ w,
                            const float* __restrict__ b) {
    int row = blockIdx.x;
    int t = threadIdx.x;
    float v = x[(size_t)row * CM + t];
    __shared__ float rs[256], rq[256];
    rs[t] = v; rq[t] = v * v;
    __syncthreads();
    for (int st = 128; st > 0; st >>= 1) {
        if (t < st) { rs[t] += rs[t + st]; rq[t] += rq[t + st]; }
        __syncthreads();
    }
    float mean = rs[0] * (1.0f / CM);
    float var  = rq[0] * (1.0f / CM) - mean * mean;
    float inv  = rsqrtf(var + LNEPS);
    g_mn[(size_t)row * CM + t] = (v - mean) * inv * w[t] + b[t];
}

// ---------------- LayerNorm over z rows (C_Z=128) fused with pair-bias projection ----------------
// bias[h][q][k] = sum_z zn[q][k][z] * Wz[z][h]; stored g_bias[(h*R + q)*R + k]
__global__ void ln_z_bias_kernel(const float* __restrict__ z, const float* __restrict__ w,
                                 const float* __restrict__ b, const float* __restrict__ Wz) {
    int qk = blockIdx.x;           // q*R + k
    int q = qk >> 8, k = qk & 255;
    int t = threadIdx.x;           // 0..127
    float v = z[(size_t)qk * CZ + t];
    __shared__ float rs[128], rq[128];
    rs[t] = v; rq[t] = v * v;
    __syncthreads();
    for (int st = 64; st > 0; st >>= 1) {
        if (t < st) { rs[t] += rs[t + st]; rq[t] += rq[t + st]; }
        __syncthreads();
    }
    float mean = rs[0] * (1.0f / CZ);
    float var  = rq[0] * (1.0f / CZ) - mean * mean;
    float zn   = (v - mean) * rsqrtf(var + LNEPS) * w[t] + b[t];

    __shared__ float red[128 * 8];
#pragma unroll
    for (int h = 0; h < 8; h++) red[t * 8 + h] = zn * Wz[t * 8 + h];
    __syncthreads();
    for (int st = 64; st > 0; st >>= 1) {
        if (t < st) {
#pragma unroll
            for (int h = 0; h < 8; h++) red[t * 8 + h] += red[(t + st) * 8 + h];
        }
        __syncthreads();
    }
    if (t < 8) g_bias[((size_t)t * R_RES + q) * R_RES + k] = red[t];
}

// ---------------- tf32 tensor-core GEMM: C(65536x256) = A(65536x256) @ B(256x256) ----------------
// fused==1: blockIdx.z selects z=0/1/2 -> q/k/v (mode 1, permuted store), z=3 -> gate (mode 2)
// fused==0: mode 3 (A = g_gate .* g_o, out = out_ext + bias)
__global__ void __launch_bounds__(256, 2) tf32gemm_kernel(
    const float* __restrict__ B0, const float* __restrict__ B1,
    const float* __restrict__ B2, const float* __restrict__ B3,
    const float* __restrict__ bias, float* __restrict__ out_ext, int fused) {

    int mode, outsel = 0;
    const float* Bw;
    if (fused) {
        int zz = blockIdx.z;
        Bw = (zz == 0) ? B0 : (zz == 1) ? B1 : (zz == 2) ? B2 : B3;
        mode = (zz == 3) ? 2 : 1;
        outsel = zz;
    } else {
        Bw = B0; mode = 3;
    }

    const float* A  = (mode == 3) ? g_gate : g_mn;
    const float* A2 = (mode == 3) ? g_o : nullptr;
    float* out;
    if (mode == 3)      out = out_ext;
    else if (mode == 2) out = g_gate;
    else                out = (outsel == 0) ? g_q : (outsel == 1) ? g_k : g_v;

    __shared__ __align__(16) float As[128 * 36];
    __shared__ __align__(16) float Bs[32 * 72];

    const int tid  = threadIdx.x;
    const int lane = tid & 31, wid = tid >> 5;
    const int gid  = lane >> 2, tg = lane & 3;
    const int wm   = (wid & 3) * 32;
    const int wn   = (wid >> 2) * 32;
    const int bx   = blockIdx.x, by = blockIdx.y;

    const int a_row = tid >> 1;
    const int a_col = (tid & 1) * 16;
    const int b_row = tid >> 3;
    const int b_col = (tid & 7) * 8;

    const float* Ap  = A + ((size_t)(by * 128 + a_row)) * 256 + a_col;
    const float* A2p = A2 ? A2 + ((size_t)(by * 128 + a_row)) * 256 + a_col : nullptr;
    const float* Bp  = Bw + (size_t)b_row * 256 + bx * 64 + b_col;

    float4 ar[4], br[2];
#pragma unroll
    for (int i = 0; i < 4; i++) ar[i] = ((const float4*)Ap)[i];
    if (A2) {
#pragma unroll
        for (int i = 0; i < 4; i++) {
            float4 g2 = ((const float4*)A2p)[i];
            ar[i].x *= g2.x; ar[i].y *= g2.y; ar[i].z *= g2.z; ar[i].w *= g2.w;
        }
    }
#pragma unroll
    for (int i = 0; i < 2; i++) br[i] = ((const float4*)Bp)[i];

    float acc[2][4][4];
#pragma unroll
    for (int mt = 0; mt < 2; mt++)
#pragma unroll
        for (int nt = 0; nt < 4; nt++)
#pragma unroll
            for (int j = 0; j < 4; j++) acc[mt][nt][j] = 0.f;

    for (int k0 = 0; k0 < 256; k0 += 32) {
#pragma unroll
        for (int i = 0; i < 4; i++) {
            float4 v = ar[i];
            v.x = ftf32(v.x); v.y = ftf32(v.y); v.z = ftf32(v.z); v.w = ftf32(v.w);
            *(float4*)&As[a_row * 36 + a_col + 4 * i] = v;
        }
#pragma unroll
        for (int i = 0; i < 2; i++) {
            float4 v = br[i];
            v.x = ftf32(v.x); v.y = ftf32(v.y); v.z = ftf32(v.z); v.w = ftf32(v.w);
            *(float4*)&Bs[b_row * 72 + b_col + 4 * i] = v;
        }
        __syncthreads();

        if (k0 < 224) {
#pragma unroll
            for (int i = 0; i < 4; i++) ar[i] = ((const float4*)(Ap + k0 + 32))[i];
            if (A2) {
#pragma unroll
                for (int i = 0; i < 4; i++) {
                    float4 g2 = ((const float4*)(A2p + k0 + 32))[i];
                    ar[i].x *= g2.x; ar[i].y *= g2.y; ar[i].z *= g2.z; ar[i].w *= g2.w;
                }
            }
#pragma unroll
            for (int i = 0; i < 2; i++) br[i] = ((const float4*)(Bp + (size_t)(k0 + 32) * 256))[i];
        }

#pragma unroll
        for (int ks = 0; ks < 4; ks++) {
            const int kb = ks * 8;
            uint32_t a[2][4], b[4][2];
#pragma unroll
            for (int mt = 0; mt < 2; mt++) {
                int r0 = wm + mt * 16 + gid;
                a[mt][0] = __float_as_uint(As[r0 * 36 + kb + tg]);
                a[mt][1] = __float_as_uint(As[(r0 + 8) * 36 + kb + tg]);
                a[mt][2] = __float_as_uint(As[r0 * 36 + kb + tg + 4]);
                a[mt][3] = __float_as_uint(As[(r0 + 8) * 36 + kb + tg + 4]);
            }
#pragma unroll
            for (int nt = 0; nt < 4; nt++) {
                int c0 = wn + nt * 8 + gid;
                b[nt][0] = __float_as_uint(Bs[(kb + tg) * 72 + c0]);
                b[nt][1] = __float_as_uint(Bs[(kb + tg + 4) * 72 + c0]);
            }
#pragma unroll
            for (int mt = 0; mt < 2; mt++)
#pragma unroll
                for (int nt = 0; nt < 4; nt++)
                    MMA4(acc[mt][nt], a[mt], b[nt]);
        }
        __syncthreads();
    }

#pragma unroll
    for (int mt = 0; mt < 2; mt++) {
#pragma unroll
        for (int nt = 0; nt < 4; nt++) {
#pragma unroll
            for (int half = 0; half < 2; half++) {
                int gr = by * 128 + wm + mt * 16 + gid + half * 8;
                int gc = bx * 64 + wn + nt * 8 + tg * 2;
                float2 val;
                val.x = acc[mt][nt][half * 2 + 0];
                val.y = acc[mt][nt][half * 2 + 1];
                if (mode == 2) {
                    val.x = 1.f / (1.f + __expf(-(val.x + bias[gc + 0])));
                    val.y = 1.f / (1.f + __expf(-(val.y + bias[gc + 1])));
                } else if (mode == 3) {
                    val.x += bias[gc + 0];
                    val.y += bias[gc + 1];
                }
                if (mode == 1) {
                    int s = gr >> 8, r = gr & 255, h = gc >> 5, c = gc & 31;
                    *(float2*)(out + (((size_t)(s * NH + h) * R_RES + r) * CH + c)) = val;
                } else {
                    *(float2*)(out + (size_t)gr * 256 + gc) = val;
                }
            }
        }
    }
}

// ---------------- tensor-core flash attention ----------------
// grid (2, S*NH): blockIdx.x = 128-row q block, blockIdx.y = s*NH+h.
// 8 warps; warp w owns query rows w*16..w*16+15 (full row span -> intra-warp softmax only).
__global__ void __launch_bounds__(256, 2) attn_mma_kernel() {
    const int sh = blockIdx.y;
    const int s = sh >> 3, h = sh & 7;
    const int qb = blockIdx.x;
    const int tid = threadIdx.x;
    const int lane = tid & 31, wid = tid >> 5;
    const int gid = lane >> 2, tg = lane & 3;
    const int wrow = wid * 16;

    __shared__ __align__(16) float Qs[128 * 36];
    __shared__ __align__(16) float Ks[64 * 36];
    __shared__ __align__(16) float Vs[64 * 40];

    // load Q tile (128 x 32) as tf32
    const float* qg = g_q + ((size_t)sh * R_RES + qb * 128) * CH;
#pragma unroll
    for (int it = 0; it < 4; it++) {
        int i = tid + it * 256;                 // 1024 float4 total
        int r = i >> 3, c4 = i & 7;
        float4 v = ((const float4*)qg)[i];
        v.x = ftf32(v.x); v.y = ftf32(v.y); v.z = ftf32(v.z); v.w = ftf32(v.w);
        *(float4*)&Qs[r * 36 + c4 * 4] = v;
    }
    __syncthreads();

    // Q A-fragments (persist across key tiles)
    uint32_t qa[4][4];
#pragma unroll
    for (int ks = 0; ks < 4; ks++) {
        int r0 = wrow + gid;
        qa[ks][0] = __float_as_uint(Qs[r0 * 36 + ks * 8 + tg]);
        qa[ks][1] = __float_as_uint(Qs[(r0 + 8) * 36 + ks * 8 + tg]);
        qa[ks][2] = __float_as_uint(Qs[r0 * 36 + ks * 8 + tg + 4]);
        qa[ks][3] = __float_as_uint(Qs[(r0 + 8) * 36 + ks * 8 + tg + 4]);
    }

    float m_i[2] = {-3.0e38f, -3.0e38f};
    float l_i[2] = {0.f, 0.f};
    float accO[4][4];
#pragma unroll
    for (int ct = 0; ct < 4; ct++)
#pragma unroll
        for (int j = 0; j < 4; j++) accO[ct][j] = 0.f;

    const float scale = 0.17677669529663687f;   // 1/sqrt(32)
    const float* bias_r0 = g_bias + ((size_t)h * R_RES + qb * 128 + wrow + gid) * R_RES;
    const float* bias_r1 = bias_r0 + 8 * R_RES;

    for (int kt = 0; kt < 4; kt++) {
        // load K/V tiles (64 x 32) as tf32; V with stride 40 (conflict-free B-frags)
        const float* kg = g_k + ((size_t)sh * R_RES + kt * 64) * CH;
        const float* vg = g_v + ((size_t)sh * R_RES + kt * 64) * CH;
#pragma unroll
        for (int it = 0; it < 2; it++) {
            int i = tid + it * 256;             // 512 float4 total
            int r = i >> 3, c4 = i & 7;
            float4 kv = ((const float4*)kg)[i];
            kv.x = ftf32(kv.x); kv.y = ftf32(kv.y); kv.z = ftf32(kv.z); kv.w = ftf32(kv.w);
            *(float4*)&Ks[r * 36 + c4 * 4] = kv;
            float4 vv = ((const float4*)vg)[i];
            vv.x = ftf32(vv.x); vv.y = ftf32(vv.y); vv.z = ftf32(vv.z); vv.w = ftf32(vv.w);
            *(float4*)&Vs[r * 40 + c4 * 4] = vv;
        }
        __syncthreads();

        // scores: 128x64 tile, per-warp 16x64
        float acc[8][4];
#pragma unroll
        for (int nt = 0; nt < 8; nt++)
#pragma unroll
            for (int j = 0; j < 4; j++) acc[nt][j] = 0.f;

#pragma unroll
        for (int nt = 0; nt < 8; nt++) {
            const float* kr = &Ks[(nt * 8 + gid) * 36 + tg];
            uint32_t b[2];
#pragma unroll
            for (int ks = 0; ks < 4; ks++) {
                b[0] = __float_as_uint(kr[ks * 8]);
                b[1] = __float_as_uint(kr[ks * 8 + 4]);
                MMA4(acc[nt], qa[ks], b);
            }
        }

        // scale + bias (batched loads; L2-resident)
        float2 bb0[8], bb1[8];
#pragma unroll
        for (int nt = 0; nt < 8; nt++) {
            int col = kt * 64 + nt * 8 + 2 * tg;
            bb0[nt] = *(const float2*)&bias_r0[col];
            bb1[nt] = *(const float2*)&bias_r1[col];
        }
#pragma unroll
        for (int nt = 0; nt < 8; nt++) {
            acc[nt][0] = fmaf(acc[nt][0], scale, bb0[nt].x);
            acc[nt][1] = fmaf(acc[nt][1], scale, bb0[nt].y);
            acc[nt][2] = fmaf(acc[nt][2], scale, bb1[nt].x);
            acc[nt][3] = fmaf(acc[nt][3], scale, bb1[nt].y);
        }

        // online softmax (rows split only across the 4-lane tg group)
        float mt[2] = {-3.0e38f, -3.0e38f};
#pragma unroll
        for (int nt = 0; nt < 8; nt++) {
            mt[0] = fmaxf(mt[0], fmaxf(acc[nt][0], acc[nt][1]));
            mt[1] = fmaxf(mt[1], fmaxf(acc[nt][2], acc[nt][3]));
        }
#pragma unroll
        for (int rh = 0; rh < 2; rh++) {
            mt[rh] = fmaxf(mt[rh], __shfl_xor_sync(0xffffffff, mt[rh], 1));
            mt[rh] = fmaxf(mt[rh], __shfl_xor_sync(0xffffffff, mt[rh], 2));
            float mnew = fmaxf(m_i[rh], mt[rh]);
            float corr = __expf(m_i[rh] - mnew);
            m_i[rh] = mnew;
            l_i[rh] *= corr;
#pragma unroll
            for (int ct = 0; ct < 4; ct++) {
                accO[ct][rh * 2 + 0] *= corr;
                accO[ct][rh * 2 + 1] *= corr;
            }
        }
#pragma unroll
        for (int nt = 0; nt < 8; nt++) {
            acc[nt][0] = __expf(acc[nt][0] - m_i[0]);
            acc[nt][1] = __expf(acc[nt][1] - m_i[0]);
            acc[nt][2] = __expf(acc[nt][2] - m_i[1]);
            acc[nt][3] = __expf(acc[nt][3] - m_i[1]);
            l_i[0] += acc[nt][0] + acc[nt][1];
            l_i[1] += acc[nt][2] + acc[nt][3];
        }

        // P@V: shuffle acc layout (cols 2tg,2tg+1) -> A-frag layout (cols tg,tg+4)
        const int src = 4 * gid + (tg >> 1);
        const bool odd = tg & 1;
#pragma unroll
        for (int nt = 0; nt < 8; nt++) {
            float v0  = __shfl_sync(0xffffffff, acc[nt][0], src);
            float v1  = __shfl_sync(0xffffffff, acc[nt][1], src);
            float w0  = __shfl_sync(0xffffffff, acc[nt][2], src);
            float w1  = __shfl_sync(0xffffffff, acc[nt][3], src);
            float v0b = __shfl_sync(0xffffffff, acc[nt][0], src + 2);
            float v1b = __shfl_sync(0xffffffff, acc[nt][1], src + 2);
            float w0b = __shfl_sync(0xffffffff, acc[nt][2], src + 2);
            float w1b = __shfl_sync(0xffffffff, acc[nt][3], src + 2);
            uint32_t pa[4];
            pa[0] = ftf32u(odd ? v1 : v0);
            pa[1] = ftf32u(odd ? w1 : w0);
            pa[2] = ftf32u(odd ? v1b : v0b);
            pa[3] = ftf32u(odd ? w1b : w0b);
            const float* vr = &Vs[(nt * 8 + tg) * 40 + gid];
            uint32_t b[2];
#pragma unroll
            for (int ct = 0; ct < 4; ct++) {
                b[0] = __float_as_uint(vr[ct * 8]);
                b[1] = __float_as_uint(vr[ct * 8 + 160]);   // +4 rows * 40
                MMA4(accO[ct], pa, b);
            }
        }
        __syncthreads();
    }

    // finalize: reduce l across tg lanes, normalize, store
    float inv[2];
#pragma unroll
    for (int rh = 0; rh < 2; rh++) {
        float l = l_i[rh];
        l += __shfl_xor_sync(0xffffffff, l, 1);
        l += __shfl_xor_sync(0xffffffff, l, 2);
        inv[rh] = 1.0f / l;
    }
#pragma unroll
    for (int ct = 0; ct < 4; ct++) {
#pragma unroll
        for (int rh = 0; rh < 2; rh++) {
            int r = qb * 128 + wrow + gid + rh * 8;
            float2 val;
            val.x = accO[ct][rh * 2 + 0] * inv[rh];
            val.y = accO[ct][rh * 2 + 1] * inv[rh];
            *(float2*)(g_o + ((size_t)s * R_RES + r) * HC + h * CH + ct * 8 + 2 * tg) = val;
        }
    }
}

// ---------------- launch ----------------
extern "C" void kernel_launch(void* const* d_in, const int* in_sizes, int n_in,
                              void* d_out, int out_size) {
    (void)in_sizes; (void)n_in; (void)out_size;
    const float* m   = (const float*)d_in[0];
    const float* z   = (const float*)d_in[1];
    const float* lmw = (const float*)d_in[2];
    const float* lmb = (const float*)d_in[3];
    const float* lzw = (const float*)d_in[4];
    const float* lzb = (const float*)d_in[5];
    const float* Wz  = (const float*)d_in[6];
    const float* Wq  = (const float*)d_in[7];
    const float* Wk  = (const float*)d_in[8];
    const float* Wv  = (const float*)d_in[9];
    const float* Wg  = (const float*)d_in[10];
    const float* bg  = (const float*)d_in[11];
    const float* Wo  = (const float*)d_in[12];
    const float* bo  = (const float*)d_in[13];

    ln_m_kernel<<<S_SEQ * R_RES, 256>>>(m, lmw, lmb);
    ln_z_bias_kernel<<<R_RES * R_RES, 128>>>(z, lzw, lzb, Wz);

    dim3 gq(4, 512, 4);   // fused q/k/v/gate
    tf32gemm_kernel<<<gq, 256>>>(Wq, Wk, Wv, Wg, bg, nullptr, 1);

    attn_mma_kernel<<<dim3(2, S_SEQ * NH), 256>>>();

    dim3 go(4, 512, 1);
    tf32gemm_kernel<<<go, 256>>>(Wo, nullptr, nullptr, nullptr, bo, (float*)d_out, 0);
}

// round 5
// speedup vs baseline: 2.5796x; 1.5516x over previous
#include <cuda_runtime.h>
#include <math.h>
#include <stdint.h>

#define S_SEQ 256
#define R_RES 256
#define CM 256
#define CZ 128
#define NH 8
#define CH 32
#define HC 256
#define LNEPS 1e-5f

// ---------------- scratch (device globals; no allocation allowed) ----------------
__device__ float g_mn[(size_t)S_SEQ * R_RES * CM];       // 64 MB  LN(m)
__device__ float g_q[(size_t)S_SEQ * NH * R_RES * CH];   // 64 MB  (s,h,r,c)
__device__ float g_k[(size_t)S_SEQ * NH * R_RES * CH];   // 64 MB
__device__ float g_v[(size_t)S_SEQ * NH * R_RES * CH];   // 64 MB
__device__ float g_gate[(size_t)S_SEQ * R_RES * HC];     // 64 MB  sigmoid(mn@Wg+bg)
__device__ float g_o[(size_t)S_SEQ * R_RES * HC];        // 64 MB  attention out (s,r,h*c)
__device__ float g_bias[(size_t)NH * R_RES * R_RES];     //  2 MB  layout [h][q][k]
__device__ float2 g_wf[5 * 32768];                       //  2.5 MB B-fragments (tf32)

__device__ __forceinline__ float ftf32(float x) {
    uint32_t u;
    asm("cvt.rna.tf32.f32 %0, %1;" : "=r"(u) : "f"(x));
    return __uint_as_float(u);
}
__device__ __forceinline__ uint32_t ftf32u(float x) {
    uint32_t u;
    asm("cvt.rna.tf32.f32 %0, %1;" : "=r"(u) : "f"(x));
    return u;
}

#define MMA4(d, a, b)                                                              \
    asm volatile("mma.sync.aligned.m16n8k8.row.col.f32.tf32.tf32.f32 "             \
                 "{%0,%1,%2,%3},{%4,%5,%6,%7},{%8,%9},{%0,%1,%2,%3};"              \
                 : "+f"(d[0]), "+f"(d[1]), "+f"(d[2]), "+f"(d[3])                  \
                 : "r"(a[0]), "r"(a[1]), "r"(a[2]), "r"(a[3]), "r"(b[0]), "r"(b[1]))

// ---------------- LayerNorm m: one warp per row (C_M = 256) ----------------
__global__ void __launch_bounds__(256) ln_m_kernel(const float* __restrict__ x,
                                                   const float* __restrict__ w,
                                                   const float* __restrict__ b) {
    const int wid = threadIdx.x >> 5, lane = threadIdx.x & 31;
    const int row = blockIdx.x * 8 + wid;
    const float* xp = x + (size_t)row * CM;
    float4 v0 = *(const float4*)(xp + 4 * lane);
    float4 v1 = *(const float4*)(xp + 4 * lane + 128);
    float s  = v0.x + v0.y + v0.z + v0.w + v1.x + v1.y + v1.z + v1.w;
    float sq = v0.x * v0.x + v0.y * v0.y + v0.z * v0.z + v0.w * v0.w
             + v1.x * v1.x + v1.y * v1.y + v1.z * v1.z + v1.w * v1.w;
#pragma unroll
    for (int st = 16; st > 0; st >>= 1) {
        s  += __shfl_xor_sync(0xffffffff, s, st);
        sq += __shfl_xor_sync(0xffffffff, sq, st);
    }
    float mean = s * (1.0f / CM);
    float inv  = rsqrtf(sq * (1.0f / CM) - mean * mean + LNEPS);
    float4 w0 = *(const float4*)(w + 4 * lane);
    float4 w1 = *(const float4*)(w + 4 * lane + 128);
    float4 b0 = *(const float4*)(b + 4 * lane);
    float4 b1 = *(const float4*)(b + 4 * lane + 128);
    float* op = g_mn + (size_t)row * CM;
    float4 o0, o1;
    o0.x = (v0.x - mean) * inv * w0.x + b0.x;
    o0.y = (v0.y - mean) * inv * w0.y + b0.y;
    o0.z = (v0.z - mean) * inv * w0.z + b0.z;
    o0.w = (v0.w - mean) * inv * w0.w + b0.w;
    o1.x = (v1.x - mean) * inv * w1.x + b1.x;
    o1.y = (v1.y - mean) * inv * w1.y + b1.y;
    o1.z = (v1.z - mean) * inv * w1.z + b1.z;
    o1.w = (v1.w - mean) * inv * w1.w + b1.w;
    *(float4*)(op + 4 * lane) = o0;
    *(float4*)(op + 4 * lane + 128) = o1;
}

// ---------------- LN(z) + pair-bias: one warp per (q,k) row ----------------
// bias[h][q][k] = sum_z zn[q][k][z] * Wz[z][h]; stored g_bias[(h*R + q)*R + k]
__global__ void __launch_bounds__(256) ln_z_bias_kernel(
    const float* __restrict__ z, const float* __restrict__ w,
    const float* __restrict__ b, const float* __restrict__ Wz) {
    __shared__ float sWzT[8 * 128];   // transposed: [h][z]
    const int tid = threadIdx.x;
    for (int i = tid; i < 1024; i += 256) {
        int zz = i >> 3, h = i & 7;
        sWzT[h * 128 + zz] = Wz[i];
    }
    __syncthreads();

    const int wid = tid >> 5, lane = tid & 31;
    const int qk = blockIdx.x * 8 + wid;
    const int q = qk >> 8, k = qk & 255;
    float4 v = *(const float4*)(z + (size_t)qk * CZ + 4 * lane);
    float s  = v.x + v.y + v.z + v.w;
    float sq = v.x * v.x + v.y * v.y + v.z * v.z + v.w * v.w;
#pragma unroll
    for (int st = 16; st > 0; st >>= 1) {
        s  += __shfl_xor_sync(0xffffffff, s, st);
        sq += __shfl_xor_sync(0xffffffff, sq, st);
    }
    float mean = s * (1.0f / CZ);
    float inv  = rsqrtf(sq * (1.0f / CZ) - mean * mean + LNEPS);
    float4 w4 = *(const float4*)(w + 4 * lane);
    float4 b4 = *(const float4*)(b + 4 * lane);
    float4 zn;
    zn.x = (v.x - mean) * inv * w4.x + b4.x;
    zn.y = (v.y - mean) * inv * w4.y + b4.y;
    zn.z = (v.z - mean) * inv * w4.z + b4.z;
    zn.w = (v.w - mean) * inv * w4.w + b4.w;

    float p[8];
#pragma unroll
    for (int h = 0; h < 8; h++) {
        float4 wz = *(const float4*)&sWzT[h * 128 + 4 * lane];
        p[h] = zn.x * wz.x + zn.y * wz.y + zn.z * wz.z + zn.w * wz.w;
    }
#pragma unroll
    for (int st = 16; st > 0; st >>= 1) {
#pragma unroll
        for (int h = 0; h < 8; h++) p[h] += __shfl_xor_sync(0xffffffff, p[h], st);
    }
    float outv = p[0];
#pragma unroll
    for (int h = 1; h < 8; h++) if (lane == h) outv = p[h];
    if (lane < 8)
        g_bias[((size_t)lane * R_RES + q) * R_RES + k] = outv;
}

// ---------------- B-fragment repack: W[k][n] -> per-lane mma fragment float2 ----------------
// g_wf index (per float2): ((((zz*8+kt)*4+ks)*8+nb)*4+nt)*32+lane
// val.x = W[kt*32+ks*8+tg][nb*32+nt*8+gid], val.y = same with k+4   (tg=lane&3, gid=lane>>2)
__global__ void __launch_bounds__(256) repack_kernel(
    const float* __restrict__ w0, const float* __restrict__ w1,
    const float* __restrict__ w2, const float* __restrict__ w3,
    const float* __restrict__ w4) {
    int t = blockIdx.x * 256 + threadIdx.x;       // < 163840
    int lane = t & 31;
    int nt = (t >> 5) & 3;
    int nb = (t >> 7) & 7;
    int ks = (t >> 10) & 3;
    int kt = (t >> 12) & 7;
    int zz = t >> 15;
    const float* W = (zz == 0) ? w0 : (zz == 1) ? w1 : (zz == 2) ? w2 : (zz == 3) ? w3 : w4;
    int krow = kt * 32 + ks * 8 + (lane & 3);
    int ncol = nb * 32 + nt * 8 + (lane >> 2);
    float2 v;
    v.x = ftf32(W[krow * 256 + ncol]);
    v.y = ftf32(W[(krow + 4) * 256 + ncol]);
    g_wf[t] = v;
}

// ---------------- tf32 tensor-core GEMM: C(65536x256) = A(65536x256) @ W ----------------
// fused==1: blockIdx.z = 0/1/2 -> q/k/v (permuted store), 3 -> gate (sigmoid+bg)
// fused==0: A = g_gate .* g_o, out = out_ext + bo   (weights slot zz=4)
// CTA tile 128x64, BK=32, 8 warps (4m x 2n), warp tile 32x32.
// B fragments from g_wf (LDG, L2-hot). A double-buffered in smem -> 1 barrier/tile.
__global__ void __launch_bounds__(256, 2) tf32gemm_kernel(
    const float* __restrict__ bias_g, const float* __restrict__ bias_o,
    float* __restrict__ out_ext, int fused) {

    const int zz = fused ? blockIdx.z : 4;
    const float* A  = fused ? g_mn : g_gate;
    const float* A2 = fused ? nullptr : g_o;
    const float* bias = fused ? bias_g : bias_o;
    float* out;
    if (!fused)          out = out_ext;
    else if (zz == 3)    out = g_gate;
    else                 out = (zz == 0) ? g_q : (zz == 1) ? g_k : g_v;

    __shared__ __align__(16) float As[2][128 * 36];

    const int tid  = threadIdx.x;
    const int lane = tid & 31, wid = tid >> 5;
    const int gid  = lane >> 2, tg = lane & 3;
    const int wm   = (wid & 3) * 32;
    const int wn   = (wid >> 2) * 32;
    const int bx   = blockIdx.x, by = blockIdx.y;
    const int nb   = bx * 2 + (wn >> 5);

    const int a_row = tid >> 1;
    const int a_col = (tid & 1) * 16;

    const float* Ap  = A + ((size_t)(by * 128 + a_row)) * 256 + a_col;
    const float* A2p = A2 ? A2 + ((size_t)(by * 128 + a_row)) * 256 + a_col : nullptr;
    const float2* wf = g_wf + (size_t)zz * 32768;

    // prologue: load tile 0 and store to buffer 0
    float4 ar[4];
#pragma unroll
    for (int i = 0; i < 4; i++) ar[i] = ((const float4*)Ap)[i];
    if (A2) {
#pragma unroll
        for (int i = 0; i < 4; i++) {
            float4 g2 = ((const float4*)A2p)[i];
            ar[i].x *= g2.x; ar[i].y *= g2.y; ar[i].z *= g2.z; ar[i].w *= g2.w;
        }
    }
#pragma unroll
    for (int i = 0; i < 4; i++) {
        float4 v = ar[i];
        v.x = ftf32(v.x); v.y = ftf32(v.y); v.z = ftf32(v.z); v.w = ftf32(v.w);
        *(float4*)&As[0][a_row * 36 + a_col + 4 * i] = v;
    }

    float acc[2][4][4];
#pragma unroll
    for (int mt = 0; mt < 2; mt++)
#pragma unroll
        for (int nt = 0; nt < 4; nt++)
#pragma unroll
            for (int j = 0; j < 4; j++) acc[mt][nt][j] = 0.f;

#pragma unroll 1
    for (int kt = 0; kt < 8; kt++) {
        const int cur = kt & 1;
        __syncthreads();

        // B fragments for this k-tile (16 LDG.64, L2-hot)
        float2 bf[4][4];
        {
            const float2* p = wf + ((size_t)kt * 4) * 1024 + (size_t)nb * 128 + lane;
#pragma unroll
            for (int ks = 0; ks < 4; ks++)
#pragma unroll
                for (int nt = 0; nt < 4; nt++)
                    bf[ks][nt] = p[ks * 1024 + nt * 32];
        }

        // prefetch next A tile into registers
        if (kt < 7) {
            const int koff = (kt + 1) * 32;
#pragma unroll
            for (int i = 0; i < 4; i++) ar[i] = ((const float4*)(Ap + koff))[i];
            if (A2) {
#pragma unroll
                for (int i = 0; i < 4; i++) {
                    float4 g2 = ((const float4*)(A2p + koff))[i];
                    ar[i].x *= g2.x; ar[i].y *= g2.y; ar[i].z *= g2.z; ar[i].w *= g2.w;
                }
            }
        }

        // compute from As[cur]
#pragma unroll
        for (int ks = 0; ks < 4; ks++) {
            const int kb = ks * 8;
            uint32_t a[2][4];
#pragma unroll
            for (int mt = 0; mt < 2; mt++) {
                int r0 = wm + mt * 16 + gid;
                a[mt][0] = __float_as_uint(As[cur][r0 * 36 + kb + tg]);
                a[mt][1] = __float_as_uint(As[cur][(r0 + 8) * 36 + kb + tg]);
                a[mt][2] = __float_as_uint(As[cur][r0 * 36 + kb + tg + 4]);
                a[mt][3] = __float_as_uint(As[cur][(r0 + 8) * 36 + kb + tg + 4]);
            }
#pragma unroll
            for (int nt = 0; nt < 4; nt++) {
                uint32_t b[2];
                b[0] = __float_as_uint(bf[ks][nt].x);
                b[1] = __float_as_uint(bf[ks][nt].y);
#pragma unroll
                for (int mt = 0; mt < 2; mt++)
                    MMA4(acc[mt][nt], a[mt], b);
            }
        }

        // store next tile into the other buffer
        if (kt < 7) {
#pragma unroll
            for (int i = 0; i < 4; i++) {
                float4 v = ar[i];
                v.x = ftf32(v.x); v.y = ftf32(v.y); v.z = ftf32(v.z); v.w = ftf32(v.w);
                *(float4*)&As[cur ^ 1][a_row * 36 + a_col + 4 * i] = v;
            }
        }
    }

    // ---- epilogue ----
#pragma unroll
    for (int mt = 0; mt < 2; mt++) {
#pragma unroll
        for (int nt = 0; nt < 4; nt++) {
#pragma unroll
            for (int half = 0; half < 2; half++) {
                int gr = by * 128 + wm + mt * 16 + gid + half * 8;
                int gc = bx * 64 + wn + nt * 8 + tg * 2;
                float2 val;
                val.x = acc[mt][nt][half * 2 + 0];
                val.y = acc[mt][nt][half * 2 + 1];
                if (fused && zz == 3) {
                    val.x = 1.f / (1.f + __expf(-(val.x + bias[gc + 0])));
                    val.y = 1.f / (1.f + __expf(-(val.y + bias[gc + 1])));
                } else if (!fused) {
                    val.x += bias[gc + 0];
                    val.y += bias[gc + 1];
                }
                if (fused && zz < 3) {
                    int s = gr >> 8, r = gr & 255, h = gc >> 5, c = gc & 31;
                    *(float2*)(out + (((size_t)(s * NH + h) * R_RES + r) * CH + c)) = val;
                } else {
                    *(float2*)(out + (size_t)gr * 256 + gc) = val;
                }
            }
        }
    }
}

// ---------------- tensor-core flash attention (R3, verified) ----------------
__global__ void __launch_bounds__(256, 2) attn_mma_kernel() {
    const int sh = blockIdx.y;
    const int s = sh >> 3, h = sh & 7;
    const int qb = blockIdx.x;
    const int tid = threadIdx.x;
    const int lane = tid & 31, wid = tid >> 5;
    const int gid = lane >> 2, tg = lane & 3;
    const int wrow = wid * 16;

    __shared__ __align__(16) float Qs[128 * 36];
    __shared__ __align__(16) float Ks[64 * 36];
    __shared__ __align__(16) float Vs[64 * 40];

    const float* qg = g_q + ((size_t)sh * R_RES + qb * 128) * CH;
#pragma unroll
    for (int it = 0; it < 4; it++) {
        int i = tid + it * 256;
        int r = i >> 3, c4 = i & 7;
        float4 v = ((const float4*)qg)[i];
        v.x = ftf32(v.x); v.y = ftf32(v.y); v.z = ftf32(v.z); v.w = ftf32(v.w);
        *(float4*)&Qs[r * 36 + c4 * 4] = v;
    }
    __syncthreads();

    uint32_t qa[4][4];
#pragma unroll
    for (int ks = 0; ks < 4; ks++) {
        int r0 = wrow + gid;
        qa[ks][0] = __float_as_uint(Qs[r0 * 36 + ks * 8 + tg]);
        qa[ks][1] = __float_as_uint(Qs[(r0 + 8) * 36 + ks * 8 + tg]);
        qa[ks][2] = __float_as_uint(Qs[r0 * 36 + ks * 8 + tg + 4]);
        qa[ks][3] = __float_as_uint(Qs[(r0 + 8) * 36 + ks * 8 + tg + 4]);
    }

    float m_i[2] = {-3.0e38f, -3.0e38f};
    float l_i[2] = {0.f, 0.f};
    float accO[4][4];
#pragma unroll
    for (int ct = 0; ct < 4; ct++)
#pragma unroll
        for (int j = 0; j < 4; j++) accO[ct][j] = 0.f;

    const float scale = 0.17677669529663687f;
    const float* bias_r0 = g_bias + ((size_t)h * R_RES + qb * 128 + wrow + gid) * R_RES;
    const float* bias_r1 = bias_r0 + 8 * R_RES;

    for (int kt = 0; kt < 4; kt++) {
        const float* kg = g_k + ((size_t)sh * R_RES + kt * 64) * CH;
        const float* vg = g_v + ((size_t)sh * R_RES + kt * 64) * CH;
#pragma unroll
        for (int it = 0; it < 2; it++) {
            int i = tid + it * 256;
            int r = i >> 3, c4 = i & 7;
            float4 kv = ((const float4*)kg)[i];
            kv.x = ftf32(kv.x); kv.y = ftf32(kv.y); kv.z = ftf32(kv.z); kv.w = ftf32(kv.w);
            *(float4*)&Ks[r * 36 + c4 * 4] = kv;
            float4 vv = ((const float4*)vg)[i];
            vv.x = ftf32(vv.x); vv.y = ftf32(vv.y); vv.z = ftf32(vv.z); vv.w = ftf32(vv.w);
            *(float4*)&Vs[r * 40 + c4 * 4] = vv;
        }
        __syncthreads();

        float acc[8][4];
#pragma unroll
        for (int nt = 0; nt < 8; nt++)
#pragma unroll
            for (int j = 0; j < 4; j++) acc[nt][j] = 0.f;

#pragma unroll
        for (int nt = 0; nt < 8; nt++) {
            const float* kr = &Ks[(nt * 8 + gid) * 36 + tg];
            uint32_t b[2];
#pragma unroll
            for (int ks = 0; ks < 4; ks++) {
                b[0] = __float_as_uint(kr[ks * 8]);
                b[1] = __float_as_uint(kr[ks * 8 + 4]);
                MMA4(acc[nt], qa[ks], b);
            }
        }

        float2 bb0[8], bb1[8];
#pragma unroll
        for (int nt = 0; nt < 8; nt++) {
            int col = kt * 64 + nt * 8 + 2 * tg;
            bb0[nt] = *(const float2*)&bias_r0[col];
            bb1[nt] = *(const float2*)&bias_r1[col];
        }
#pragma unroll
        for (int nt = 0; nt < 8; nt++) {
            acc[nt][0] = fmaf(acc[nt][0], scale, bb0[nt].x);
            acc[nt][1] = fmaf(acc[nt][1], scale, bb0[nt].y);
            acc[nt][2] = fmaf(acc[nt][2], scale, bb1[nt].x);
            acc[nt][3] = fmaf(acc[nt][3], scale, bb1[nt].y);
        }

        float mt[2] = {-3.0e38f, -3.0e38f};
#pragma unroll
        for (int nt = 0; nt < 8; nt++) {
            mt[0] = fmaxf(mt[0], fmaxf(acc[nt][0], acc[nt][1]));
            mt[1] = fmaxf(mt[1], fmaxf(acc[nt][2], acc[nt][3]));
        }
#pragma unroll
        for (int rh = 0; rh < 2; rh++) {
            mt[rh] = fmaxf(mt[rh], __shfl_xor_sync(0xffffffff, mt[rh], 1));
            mt[rh] = fmaxf(mt[rh], __shfl_xor_sync(0xffffffff, mt[rh], 2));
            float mnew = fmaxf(m_i[rh], mt[rh]);
            float corr = __expf(m_i[rh] - mnew);
            m_i[rh] = mnew;
            l_i[rh] *= corr;
#pragma unroll
            for (int ct = 0; ct < 4; ct++) {
                accO[ct][rh * 2 + 0] *= corr;
                accO[ct][rh * 2 + 1] *= corr;
            }
        }
#pragma unroll
        for (int nt = 0; nt < 8; nt++) {
            acc[nt][0] = __expf(acc[nt][0] - m_i[0]);
            acc[nt][1] = __expf(acc[nt][1] - m_i[0]);
            acc[nt][2] = __expf(acc[nt][2] - m_i[1]);
            acc[nt][3] = __expf(acc[nt][3] - m_i[1]);
            l_i[0] += acc[nt][0] + acc[nt][1];
            l_i[1] += acc[nt][2] + acc[nt][3];
        }

        const int src = 4 * gid + (tg >> 1);
        const bool odd = tg & 1;
#pragma unroll
        for (int nt = 0; nt < 8; nt++) {
            float v0  = __shfl_sync(0xffffffff, acc[nt][0], src);
            float v1  = __shfl_sync(0xffffffff, acc[nt][1], src);
            float w0  = __shfl_sync(0xffffffff, acc[nt][2], src);
            float w1  = __shfl_sync(0xffffffff, acc[nt][3], src);
            float v0b = __shfl_sync(0xffffffff, acc[nt][0], src + 2);
            float v1b = __shfl_sync(0xffffffff, acc[nt][1], src + 2);
            float w0b = __shfl_sync(0xffffffff, acc[nt][2], src + 2);
            float w1b = __shfl_sync(0xffffffff, acc[nt][3], src + 2);
            uint32_t pa[4];
            pa[0] = ftf32u(odd ? v1 : v0);
            pa[1] = ftf32u(odd ? w1 : w0);
            pa[2] = ftf32u(odd ? v1b : v0b);
            pa[3] = ftf32u(odd ? w1b : w0b);
            const float* vr = &Vs[(nt * 8 + tg) * 40 + gid];
            uint32_t b[2];
#pragma unroll
            for (int ct = 0; ct < 4; ct++) {
                b[0] = __float_as_uint(vr[ct * 8]);
                b[1] = __float_as_uint(vr[ct * 8 + 160]);
                MMA4(accO[ct], pa, b);
            }
        }
        __syncthreads();
    }

    float inv[2];
#pragma unroll
    for (int rh = 0; rh < 2; rh++) {
        float l = l_i[rh];
        l += __shfl_xor_sync(0xffffffff, l, 1);
        l += __shfl_xor_sync(0xffffffff, l, 2);
        inv[rh] = 1.0f / l;
    }
#pragma unroll
    for (int ct = 0; ct < 4; ct++) {
#pragma unroll
        for (int rh = 0; rh < 2; rh++) {
            int r = qb * 128 + wrow + gid + rh * 8;
            float2 val;
            val.x = accO[ct][rh * 2 + 0] * inv[rh];
            val.y = accO[ct][rh * 2 + 1] * inv[rh];
            *(float2*)(g_o + ((size_t)s * R_RES + r) * HC + h * CH + ct * 8 + 2 * tg) = val;
        }
    }
}

// ---------------- launch ----------------
extern "C" void kernel_launch(void* const* d_in, const int* in_sizes, int n_in,
                              void* d_out, int out_size) {
    (void)in_sizes; (void)n_in; (void)out_size;
    const float* m   = (const float*)d_in[0];
    const float* z   = (const float*)d_in[1];
    const float* lmw = (const float*)d_in[2];
    const float* lmb = (const float*)d_in[3];
    const float* lzw = (const float*)d_in[4];
    const float* lzb = (const float*)d_in[5];
    const float* Wz  = (const float*)d_in[6];
    const float* Wq  = (const float*)d_in[7];
    const float* Wk  = (const float*)d_in[8];
    const float* Wv  = (const float*)d_in[9];
    const float* Wg  = (const float*)d_in[10];
    const float* bg  = (const float*)d_in[11];
    const float* Wo  = (const float*)d_in[12];
    const float* bo  = (const float*)d_in[13];

    ln_m_kernel<<<8192, 256>>>(m, lmw, lmb);
    ln_z_bias_kernel<<<8192, 256>>>(z, lzw, lzb, Wz);
    repack_kernel<<<640, 256>>>(Wq, Wk, Wv, Wg, Wo);

    tf32gemm_kernel<<<dim3(4, 512, 4), 256>>>(bg, nullptr, nullptr, 1);

    attn_mma_kernel<<<dim3(2, S_SEQ * NH), 256>>>();

    tf32gemm_kernel<<<dim3(4, 512, 1), 256>>>(nullptr, bo, (float*)d_out, 0);
}